// round 3
// baseline (speedup 1.0000x reference)
#include <cuda_runtime.h>
#include <cstdint>

#define Bb 32
#define Cc 32
#define Tt 2048
#define Dd 512
#define ALPHA 0.1f
#define BETA  0.9f

#define SEG   256      // scan segment length
#define NSEG  (Tt / SEG)

// Scratch (no cudaMalloc allowed)
__device__ float g_sA[Bb*Cc*Tt];      // 0.5 * forward EWMA of diff   [b][c][t]
__device__ float g_sB[Bb*Cc*Tt];      // 0.5 * backward EWMA of diff  [b][c][t]
__device__ float g_wcomb[Dd*Cc];      // (W_lin @ W_ve)[e][c]
__device__ float g_bcomb[Dd];         // W_lin @ b_ve + b_lin

#define FMA_F32X2(d, a, b, c) \
    asm("fma.rn.f32x2 %0, %1, %2, %3;" : "=l"(d) : "l"(a), "l"(b), "l"(c))

static __device__ __forceinline__ float2 unpack_f32x2(unsigned long long v) {
    float2 r;
    asm("mov.b64 {%0, %1}, %2;" : "=f"(r.x), "=f"(r.y) : "l"(v));
    return r;
}

// ---------------------------------------------------------------------------
// P: compose linears. One block per output row e.
// ---------------------------------------------------------------------------
__global__ void __launch_bounds__(256) prep_kernel(
    const float* __restrict__ W_ve, const float* __restrict__ b_ve,
    const float* __restrict__ W_lin, const float* __restrict__ b_lin)
{
    __shared__ float wl[Dd];
    int e = blockIdx.x;
    int tid = threadIdx.x;
    wl[tid]       = W_lin[(size_t)e * Dd + tid];
    wl[tid + 256] = W_lin[(size_t)e * Dd + tid + 256];
    __syncthreads();

    int wj   = tid >> 5;
    int lane = tid & 31;
    const unsigned FULL = 0xffffffffu;

    for (int c = wj; c <= Cc; c += 8) {
        float acc = 0.f;
        if (c < Cc) {
            #pragma unroll
            for (int i = 0; i < 16; i++) {
                int d = lane + 32 * i;
                acc = fmaf(wl[d], W_ve[d * Cc + c], acc);
            }
        } else {
            #pragma unroll
            for (int i = 0; i < 16; i++) {
                int d = lane + 32 * i;
                acc = fmaf(wl[d], b_ve[d], acc);
            }
        }
        acc += __shfl_down_sync(FULL, acc, 16);
        acc += __shfl_down_sync(FULL, acc, 8);
        acc += __shfl_down_sync(FULL, acc, 4);
        acc += __shfl_down_sync(FULL, acc, 2);
        acc += __shfl_down_sync(FULL, acc, 1);
        if (lane == 0) {
            if (c < Cc) g_wcomb[e * Cc + c] = acc;
            else        g_bcomb[e] = acc + b_lin[e];
        }
    }
}

// ---------------------------------------------------------------------------
// S: bidirectional EWMA of first-difference. Lane-serial formulation:
// each lane handles 8 consecutive elements (serial FMA chain, lat 4), then a
// 5-shfl factored Kogge-Stone over lane totals (factor beta^8), then an 8-FMA
// correction. One warp per (row, segment, direction); warm-up tile of 256
// elements for interior segments (beta^256 ~ 2e-12, far below tolerance).
// ---------------------------------------------------------------------------
__global__ void __launch_bounds__(256) scan_kernel(const float* __restrict__ x)
{
    const unsigned FULL = 0xffffffffu;
    int g    = blockIdx.x * 8 + (threadIdx.x >> 5);
    int lane = threadIdx.x & 31;
    int bc   = g >> 4;           // row (b*Cc + c)
    int rem  = g & 15;
    int seg  = rem >> 1;
    int dir  = rem & 1;

    const float* row = x + (size_t)bc * Tt;
    int lo = seg * SEG;
    int hi = lo + SEG;

    // q = beta^8 and its squarings; blE = beta^(8*lane)
    const float q   = 0.43046721f;              // 0.9^8
    const float q2  = q * q;
    const float q4  = q2 * q2;
    const float q8  = q4 * q4;
    const float q16 = q8 * q8;
    float blE;
    {
        float p = 1.f, base = q;
        int n = lane;
        while (n) { if (n & 1) p *= base; base *= base; n >>= 1; }
        blE = p;
    }
    const float B256 = 1.9e-12f;                // ~0.9^256 (negligible, kept)

    if (dir == 0) {
        float* srow = g_sA + (size_t)bc * Tt;
        int t0 = (seg == 0) ? lo : (lo - SEG);
        float warpCarry = 0.f;
        for (; t0 < hi; t0 += SEG) {
            int tb = t0 + lane * 8;
            float4 a  = *(const float4*)(row + tb);
            float4 bq = *(const float4*)(row + tb + 4);
            float e[8] = {a.x, a.y, a.z, a.w, bq.x, bq.y, bq.z, bq.w};
            float prev = __shfl_up_sync(FULL, bq.w, 1);
            if (lane == 0) prev = (tb > 0) ? row[tb - 1] : 0.f;

            float L[8];
            L[0] = (tb == 0) ? 0.f : ALPHA * (e[0] - prev);
            #pragma unroll
            for (int j = 1; j < 8; j++)
                L[j] = fmaf(BETA, L[j - 1], ALPHA * (e[j] - e[j - 1]));

            float v = L[7], vo;
            vo = __shfl_up_sync(FULL, v, 1);  if (lane >= 1)  v = fmaf(q,   vo, v);
            vo = __shfl_up_sync(FULL, v, 2);  if (lane >= 2)  v = fmaf(q2,  vo, v);
            vo = __shfl_up_sync(FULL, v, 4);  if (lane >= 4)  v = fmaf(q4,  vo, v);
            vo = __shfl_up_sync(FULL, v, 8);  if (lane >= 8)  v = fmaf(q8,  vo, v);
            vo = __shfl_up_sync(FULL, v, 16); if (lane >= 16) v = fmaf(q16, vo, v);
            float vprev = __shfl_up_sync(FULL, v, 1);
            if (lane == 0) vprev = 0.f;
            float C = fmaf(blE, warpCarry, vprev);

            float F[8];
            {
                float coef = BETA;
                #pragma unroll
                for (int j = 0; j < 8; j++) { F[j] = fmaf(coef, C, L[j]); coef *= BETA; }
            }
            float v31 = __shfl_sync(FULL, v, 31);
            warpCarry = fmaf(B256, warpCarry, v31);

            if (t0 >= lo) {
                float4 o0 = make_float4(0.5f*F[0], 0.5f*F[1], 0.5f*F[2], 0.5f*F[3]);
                float4 o1 = make_float4(0.5f*F[4], 0.5f*F[5], 0.5f*F[6], 0.5f*F[7]);
                *(float4*)(srow + tb)     = o0;
                *(float4*)(srow + tb + 4) = o1;
            }
        }
    } else {
        float* srow = g_sB + (size_t)bc * Tt;
        bool last = (hi == Tt);
        int tt = last ? (Tt - 1) : (hi + SEG - 1);
        float warpCarry = last ? (row[Tt - 1] - row[Tt - 2]) : 0.f;
        for (; tt >= lo; tt -= SEG) {
            int tb = tt - lane * 8;   // highest t of this lane; mem [tb-7, tb]
            float4 a  = *(const float4*)(row + tb - 7);  // x[tb-7..tb-4]
            float4 bq = *(const float4*)(row + tb - 3);  // x[tb-3..tb]
            // processing order j: t = tb - j
            float e[8] = {bq.w, bq.z, bq.y, bq.x, a.w, a.z, a.y, a.x};
            float prev = __shfl_down_sync(FULL, bq.w, 1);  // lane+1's e[0]? no:
            // lane+1's top element is x[tb-8]; its e[0] = its bq.w = x[(tb-8)]
            if (lane == 31) prev = (tb - 8 >= 0) ? row[tb - 8] : 0.f;

            float L[8];
            L[0] = ALPHA * (e[0] - e[1]);
            #pragma unroll
            for (int j = 1; j < 7; j++)
                L[j] = fmaf(BETA, L[j - 1], ALPHA * (e[j] - e[j + 1]));
            {
                float d7 = (tb - 7 == 0) ? 0.f : (e[7] - prev);
                L[7] = fmaf(BETA, L[6], ALPHA * d7);
            }

            float v = L[7], vo;
            vo = __shfl_up_sync(FULL, v, 1);  if (lane >= 1)  v = fmaf(q,   vo, v);
            vo = __shfl_up_sync(FULL, v, 2);  if (lane >= 2)  v = fmaf(q2,  vo, v);
            vo = __shfl_up_sync(FULL, v, 4);  if (lane >= 4)  v = fmaf(q4,  vo, v);
            vo = __shfl_up_sync(FULL, v, 8);  if (lane >= 8)  v = fmaf(q8,  vo, v);
            vo = __shfl_up_sync(FULL, v, 16); if (lane >= 16) v = fmaf(q16, vo, v);
            float vprev = __shfl_up_sync(FULL, v, 1);
            if (lane == 0) vprev = 0.f;
            float C = fmaf(blE, warpCarry, vprev);

            float F[8];
            {
                float coef = BETA;
                #pragma unroll
                for (int j = 0; j < 8; j++) { F[j] = fmaf(coef, C, L[j]); coef *= BETA; }
            }
            float v31 = __shfl_sync(FULL, v, 31);
            warpCarry = fmaf(B256, warpCarry, v31);

            if (tt < hi) {
                float4 o0 = make_float4(0.5f*F[7], 0.5f*F[6], 0.5f*F[5], 0.5f*F[4]);
                float4 o1 = make_float4(0.5f*F[3], 0.5f*F[2], 0.5f*F[1], 0.5f*F[0]);
                *(float4*)(srow + tb - 7) = o0;
                *(float4*)(srow + tb - 3) = o1;
            }
        }
    }
}

// ---------------------------------------------------------------------------
// G: out[b,t,e] = sum_c (sA+sB)[b,c,t] * Wcomb[e,c] + bcomb[e]
// FFMA2 (fma.rn.f32x2) mainloop. s tile is stored duplicated as (v,v) float2
// so broadcast operands come straight from shared memory; w pairs come from
// contiguous LDS.128. Per thread per c: 16 FFMA2 instead of 32 FFMA.
// Block tile 64 t x 512 e (4 chunks of 128 e). 256 threads, 8t x 4e each.
// ---------------------------------------------------------------------------
__global__ void __launch_bounds__(256) gemm_kernel(float* __restrict__ out)
{
    __shared__ float2 dssm[Cc][66];   // [c][t_local] duplicated pairs, 528B rows
    __shared__ float  wsm[Cc][132];   // [c][e_local], 528B rows

    int tx = threadIdx.x & 31;        // -> e (4 each)
    int ty = threadIdx.x >> 5;        // -> t (8 each)
    int tid = threadIdx.x;
    int b = blockIdx.y;
    int tBase = blockIdx.x * 64;

    // Load s tile: 32c x 64t, sum fwd+bwd, duplicate into float2 pairs.
    #pragma unroll
    for (int r = 0; r < 2; r++) {
        int idx = tid + r * 256;          // 0..511
        int c   = idx >> 4;               // 0..31
        int tl  = (idx & 15) * 4;         // 0..60
        size_t off = ((size_t)(b * Cc + c)) * Tt + tBase + tl;
        float4 a  = *(const float4*)(g_sA + off);
        float4 bq = *(const float4*)(g_sB + off);
        float v0 = a.x + bq.x, v1 = a.y + bq.y, v2 = a.z + bq.z, v3 = a.w + bq.w;
        float4* dst = (float4*)&dssm[c][tl];
        dst[0] = make_float4(v0, v0, v1, v1);
        dst[1] = make_float4(v2, v2, v3, v3);
    }

    for (int ch = 0; ch < 4; ch++) {
        int eBase = ch * 128;
        __syncthreads();   // protect wsm from prev-chunk readers; first-iter dssm
        #pragma unroll
        for (int r = 0; r < 4; r++) {
            int idx = tid + r * 256;      // 0..1023
            int el  = idx >> 3;           // 0..127
            int c4  = (idx & 7) * 4;
            float4 w = *(const float4*)(g_wcomb + (size_t)(eBase + el) * Cc + c4);
            wsm[c4 + 0][el] = w.x;
            wsm[c4 + 1][el] = w.y;
            wsm[c4 + 2][el] = w.z;
            wsm[c4 + 3][el] = w.w;
        }
        __syncthreads();

        unsigned long long acc[8][2];
        #pragma unroll
        for (int i = 0; i < 8; i++) { acc[i][0] = 0ull; acc[i][1] = 0ull; }

        #pragma unroll
        for (int c = 0; c < Cc; c++) {
            const unsigned long long* sp =
                (const unsigned long long*)&dssm[c][ty * 8];
            const unsigned long long* wq =
                (const unsigned long long*)&wsm[c][tx * 4];
            unsigned long long wp0 = wq[0];
            unsigned long long wp1 = wq[1];
            #pragma unroll
            for (int i = 0; i < 8; i++) {
                unsigned long long sv = sp[i];
                FMA_F32X2(acc[i][0], sv, wp0, acc[i][0]);
                FMA_F32X2(acc[i][1], sv, wp1, acc[i][1]);
            }
        }

        float4 bias = *(const float4*)(g_bcomb + eBase + tx * 4);
        #pragma unroll
        for (int i = 0; i < 8; i++) {
            int t = tBase + ty * 8 + i;
            float2 r0 = unpack_f32x2(acc[i][0]);
            float2 r1 = unpack_f32x2(acc[i][1]);
            float4 o;
            o.x = r0.x + bias.x;
            o.y = r0.y + bias.y;
            o.z = r1.x + bias.z;
            o.w = r1.y + bias.w;
            *(float4*)(out + ((size_t)(b * Tt + t)) * Dd + eBase + tx * 4) = o;
        }
    }
}

// ---------------------------------------------------------------------------
extern "C" void kernel_launch(void* const* d_in, const int* in_sizes, int n_in,
                              void* d_out, int out_size)
{
    const float* x     = (const float*)d_in[0];   // [B, C, T]
    const float* W_ve  = (const float*)d_in[1];   // [D, C]
    const float* b_ve  = (const float*)d_in[2];   // [D]
    const float* W_lin = (const float*)d_in[3];   // [D, D]
    const float* b_lin = (const float*)d_in[4];   // [D]
    float* out = (float*)d_out;                   // [B, T, D]

    // S: 16384 segment-warps (rows x 8 segs x 2 dirs), 8 warps/block
    scan_kernel<<<(Bb * Cc * NSEG * 2) / 8, 256>>>(x);

    // P: compose linears
    prep_kernel<<<Dd, 256>>>(W_ve, b_ve, W_lin, b_lin);

    // G: final K=32 GEMM + bias (FFMA2)
    dim3 grid(Tt / 64, Bb);
    gemm_kernel<<<grid, 256>>>(out);
}